// round 13
// baseline (speedup 1.0000x reference)
#include <cuda_runtime.h>

#define MAXN 1600000
#define MAXB 8
#define PRE_K 6000
#define POST_K 1000
#define MASKW 94            // ceil(6000/64) words per mask row
#define MW 1536             // phase-1 NMS scan/mask window
#define MWW 24              // MW/64
#define C1SPLIT 1536        // A/B split target == scan window
#define NBINS 4096
#define CAPA 2048           // A sorted by 2048-wide bitonic
#define CAPB 8192           // B sorted by 8192-wide bitonic (fallback only)
#define NEGV  -1000000000.0f

// ---------------- static device scratch (no allocations allowed) ----------------
__device__ float              g_score[MAXN];          // valid ? logit : NEGV
__device__ unsigned int       g_hist[MAXB * NBINS];
__device__ int                g_segstart[MAXB + 1];
__device__ int                g_t[MAXB];
__device__ int                g_t2[MAXB];
__device__ unsigned int       g_cntA[MAXB];
__device__ unsigned int       g_cntB[MAXB];
__device__ unsigned long long g_bufA[(size_t)MAXB * CAPA];
__device__ unsigned long long g_bufB[(size_t)MAXB * CAPB];
__device__ float4             g_cboxes[MAXB * PRE_K];
__device__ int                g_cidx[MAXB * PRE_K];
__device__ unsigned long long g_sranyb[MAXB * MASKW];  // "row suppresses someone" bits
__device__ unsigned long long g_mask[(size_t)MAXB * MASKW * PRE_K]; // TRANSPOSED [b][word][row]
__device__ int                g_kept[MAXB * POST_K];
__device__ int                g_done[MAXB];

// ---------------- XLA-exact sigmoid: 0.5 + 0.5*tanh(0.5x), fast-tanh poly ------
__device__ __forceinline__ float xla_tanh(float x) {
    float ax = fabsf(x);
    float xc = fminf(fmaxf(x, -7.99881172180175781f), 7.99881172180175781f);
    float x2 = __fmul_rn(xc, xc);
    float p = fmaf(x2, -2.76076847742355e-16f, 2.00018790482477e-13f);
    p = fmaf(p, x2, -8.60467152213735e-11f);
    p = fmaf(p, x2,  5.12229709037114e-08f);
    p = fmaf(p, x2,  1.48572235717979e-05f);
    p = fmaf(p, x2,  6.37261928875436e-04f);
    p = fmaf(p, x2,  4.89352455891786e-03f);
    float num = __fmul_rn(xc, p);
    float q = fmaf(x2, 1.19825839466702e-06f, 1.18534705686654e-04f);
    q = fmaf(q, x2, 2.26843463243900e-03f);
    q = fmaf(q, x2, 4.89352518554385e-03f);
    float r = __fdiv_rn(num, q);
    return (ax < 0.0004f) ? x : r;
}
__device__ __forceinline__ float xla_sigmoid(float x) {
    float t = xla_tanh(__fmul_rn(0.5f, x));
    return __fadd_rn(__fmul_rn(0.5f, t), 0.5f);
}

// monotone logit-space bin; bin 0 reserved for invalid (never consulted, g_t >= 1)
__device__ __forceinline__ int logit_bin(float lg) {
    int v = (int)__fmul_rn(__fadd_rn(lg, 6.0f), 341.0f);
    if (v < 1) v = 1;
    if (v > NBINS - 1) v = NBINS - 1;
    return v;
}
__device__ __forceinline__ unsigned score_key(float s) {
    unsigned ub = __float_as_uint(s);
    return (ub & 0x80000000u) ? ~ub : (ub | 0x80000000u);
}
// image id from sorted batch_indices boundaries (7 L1-hot compares)
__device__ __forceinline__ int find_b(int i, int B) {
    int b = 0;
    #pragma unroll
    for (int k = 1; k < MAXB; k++)
        if (k < B && i >= g_segstart[k]) b = k;
    return b;
}
// r-th (0-based) set bit of a 64-bit mask
__device__ __forceinline__ int fns64(unsigned long long m, int r) {
    unsigned lo = (unsigned)m;
    int pl = __popc(lo);
    if (r < pl) return (int)__fns(lo, 0, r + 1);
    return 32 + (int)__fns((unsigned)(m >> 32), 0, r - pl + 1);
}

// exact reference box decode
__device__ __forceinline__ float4 decode_box(float4 a, float4 d, float W, float H,
                                             bool& valid)
{
    float aw = __fsub_rn(a.z, a.x);
    float ah = __fsub_rn(a.w, a.y);
    float ax = __fadd_rn(a.x, __fmul_rn(0.5f, aw));
    float ay = __fadd_rn(a.y, __fmul_rn(0.5f, ah));
    float px = __fadd_rn(ax, __fmul_rn(d.x, aw));
    float py = __fadd_rn(ay, __fmul_rn(d.y, ah));
    float twc = fminf(fmaxf(d.z, -10.0f), 10.0f);
    float thc = fminf(fmaxf(d.w, -10.0f), 10.0f);
    float pw = __fmul_rn(aw, expf(twc));
    float ph = __fmul_rn(ah, expf(thc));
    float x1 = __fsub_rn(px, __fmul_rn(0.5f, pw));
    float y1 = __fsub_rn(py, __fmul_rn(0.5f, ph));
    float x2 = __fadd_rn(px, __fmul_rn(0.5f, pw));
    float y2 = __fadd_rn(py, __fmul_rn(0.5f, ph));
    float Wm1 = __fsub_rn(W, 1.0f);
    float Hm1 = __fsub_rn(H, 1.0f);
    x1 = fminf(fmaxf(x1, 0.0f), Wm1);
    y1 = fminf(fmaxf(y1, 0.0f), Hm1);
    x2 = fminf(fmaxf(x2, 0.0f), Wm1);
    y2 = fminf(fmaxf(y2, 0.0f), Hm1);
    valid = (__fsub_rn(x2, x1) >= 16.0f) && (__fsub_rn(y2, y1) >= 16.0f);
    return make_float4(x1, y1, x2, y2);
}

// ---------------- bitonic sort of NS u64 keys in shared memory (1024 thr) ------
template<int NS>
__device__ __forceinline__ void bitonic_sort(unsigned long long* sk)
{
    #pragma unroll 1
    for (int k = 2; k <= NS; k <<= 1) {
        #pragma unroll 1
        for (int j = k >> 1; j > 0; j >>= 1) {
            #pragma unroll
            for (int it = 0; it < NS / 2 / 1024; it++) {
                int t = threadIdx.x + it * 1024;
                int i = ((t & ~(j - 1)) << 1) | (t & (j - 1));
                int p = i + j;
                bool up = ((i & k) == 0);
                unsigned long long a = sk[i], c = sk[p];
                if ((a > c) == up) { sk[i] = c; sk[p] = a; }
            }
            __syncthreads();
        }
    }
}

// ---------------- launches 0/1: init -------------------------------------------
__global__ void k_init1(int B)
{
    int t = blockIdx.x * blockDim.x + threadIdx.x;
    if (t < B * NBINS / 2) g_hist[t] = 0;
}
__global__ void k_init2(int B)
{
    int t = blockIdx.x * blockDim.x + threadIdx.x;
    if (t < B * NBINS / 2) g_hist[B * NBINS / 2 + t] = 0;
    if (t < B * MASKW) g_sranyb[t] = 0ull;
}
// ---------------- launch 2: segment boundaries (batch_indices sorted) ----------
__global__ void k_segstart(const int* __restrict__ bi, int N, int B)
{
    int t = threadIdx.x;
    if (t > B) return;
    if (t == B) { g_segstart[B] = N; return; }
    int lo = 0, hi = N;
    while (lo < hi) { int mid = (lo + hi) >> 1; if (bi[mid] < t) lo = mid + 1; else hi = mid; }
    g_segstart[t] = lo;
}

// ---------------- launch 3 (profiled): decode, 4 elems/thread ------------------
__global__ __launch_bounds__(256)
void k_decode(const float4* __restrict__ anchors, const int* __restrict__ sizes,
              const float* __restrict__ logits, const float4* __restrict__ deltas,
              int N, int B)
{
    int base = (blockIdx.x * blockDim.x + threadIdx.x) * 4;
    if (base >= N) return;
    if (base + 4 <= N) {
        float4 a0 = anchors[base],   a1 = anchors[base+1],
               a2 = anchors[base+2], a3 = anchors[base+3];
        float4 d0 = deltas[base],    d1 = deltas[base+1],
               d2 = deltas[base+2],  d3 = deltas[base+3];
        float4 lg = *(const float4*)(logits + base);
        float4 a[4] = {a0, a1, a2, a3};
        float4 d[4] = {d0, d1, d2, d3};
        float lgs[4] = {lg.x, lg.y, lg.z, lg.w};
        float sc[4];
        #pragma unroll
        for (int e = 0; e < 4; e++) {
            int b = find_b(base + e, B);
            float H = (float)sizes[2 * b];
            float W = (float)sizes[2 * b + 1];
            bool valid;
            decode_box(a[e], d[e], W, H, valid);
            sc[e] = valid ? lgs[e] : NEGV;
            if (valid)
                atomicAdd(&g_hist[b * NBINS + logit_bin(lgs[e])], 1u);
        }
        *(float4*)(g_score + base) = make_float4(sc[0], sc[1], sc[2], sc[3]);
    } else {
        for (int i = base; i < N; i++) {
            int b = find_b(i, B);
            float H = (float)sizes[2 * b];
            float W = (float)sizes[2 * b + 1];
            bool valid;
            decode_box(anchors[i], deltas[i], W, H, valid);
            float lg = logits[i];
            g_score[i] = valid ? lg : NEGV;
            if (valid)
                atomicAdd(&g_hist[b * NBINS + logit_bin(lg)], 1u);
        }
    }
}

// ---------------- thresholds ---------------------------------------------------
__global__ __launch_bounds__(256)
void k_thresh()
{
    int b = blockIdx.x;
    int t = threadIdx.x;
    unsigned v[16]; unsigned s = 0;
    for (int k = 0; k < 16; k++) {
        v[k] = g_hist[b * NBINS + (NBINS - 1 - (t * 16 + k))];
        s += v[k];
    }
    __shared__ unsigned ps[256];
    __shared__ int s_t, s_t2;
    if (t == 0) { s_t = 1; s_t2 = 1; }
    ps[t] = s; __syncthreads();
    for (int off = 1; off < 256; off <<= 1) {
        unsigned x = (t >= off) ? ps[t - off] : 0u;
        __syncthreads();
        ps[t] += x;
        __syncthreads();
    }
    unsigned cum = ps[t] - s;        // exclusive prefix (descending bins)
    for (int k = 0; k < 16; k++) {
        unsigned nc = cum + v[k];
        int bin = NBINS - 1 - (t * 16 + k);
        if (cum < C1SPLIT && nc >= C1SPLIT) s_t2 = bin;
        if (cum < PRE_K   && nc >= PRE_K)   s_t  = bin;
        cum = nc;
    }
    __syncthreads();
    if (t == 0) {
        int tt = s_t, tt2 = s_t2;
        if (tt < 1) tt = 1;
        if (tt2 <= tt) tt2 = tt + 1;
        g_t[b] = tt; g_t2[b] = tt2;
        g_cntA[b] = 0; g_cntB[b] = 0;
        g_done[b] = 0;
    }
}

// ---------------- compact candidates (sigmoid only here) -----------------------
__global__ __launch_bounds__(256)
void k_compact(int N, int B)
{
    int base = (blockIdx.x * blockDim.x + threadIdx.x) * 4;
    if (base >= N) return;
    float4 s4 = *(const float4*)(g_score + base);
    float sv[4] = {s4.x, s4.y, s4.z, s4.w};
    #pragma unroll
    for (int k = 0; k < 4; k++) {
        int i = base + k;
        bool pass = false;
        int b = 0; bool toA = false;
        if (i < N && sv[k] > -1e8f) {
            b = find_b(i, B);
            int bin = logit_bin(sv[k]);
            if (bin >= g_t[b]) { pass = true; toA = (bin >= g_t2[b]); }
        }
        unsigned am = __activemask();
        unsigned grp = __ballot_sync(am, pass);
        if (!pass) continue;
        unsigned same = __match_any_sync(grp, b * 2 + (toA ? 1 : 0)) & grp;
        int leader = __ffs(same) - 1;
        int lane = threadIdx.x & 31;
        unsigned pos = 0;
        unsigned* ctr = toA ? &g_cntA[b] : &g_cntB[b];
        if (lane == leader) pos = atomicAdd(ctr, (unsigned)__popc(same));
        pos = __shfl_sync(grp, pos, leader);
        pos += __popc(same & ((1u << lane) - 1u));
        unsigned long long key =
            ((unsigned long long)(~score_key(xla_sigmoid(sv[k]))) << 21) | (unsigned)i;
        if (toA) { if (pos < CAPA) g_bufA[(size_t)b * CAPA + pos] = key; }
        else     { if (pos < CAPB) g_bufB[(size_t)b * CAPB + pos] = key; }
    }
}

// ---------------- sort A (2048 bitonic) + recompute candidate boxes ------------
__global__ __launch_bounds__(1024)
void k_sortA(const float4* __restrict__ anchors, const int* __restrict__ sizes,
             const float4* __restrict__ deltas)
{
    __shared__ unsigned long long sk[CAPA];
    int b = blockIdx.x;
    unsigned cnt = min(g_cntA[b], (unsigned)CAPA);
    for (int p = threadIdx.x; p < CAPA; p += 1024)
        sk[p] = (p < (int)cnt) ? g_bufA[(size_t)b * CAPA + p] : ~0ull;
    __syncthreads();
    bitonic_sort<CAPA>(sk);
    float H = (float)sizes[2 * b];
    float W = (float)sizes[2 * b + 1];
    for (int p = threadIdx.x; p < (int)cnt; p += 1024) {
        int gi = (int)(sk[p] & 0x1FFFFFu);
        bool valid;
        float4 box = decode_box(anchors[gi], deltas[gi], W, H, valid);
        g_cidx[b * PRE_K + p] = gi;
        g_cboxes[b * PRE_K + p] = box;
    }
}

// ---------------- sort B (8192 bitonic, fallback only) -------------------------
__global__ __launch_bounds__(1024)
void k_sortB(const float4* __restrict__ anchors, const int* __restrict__ sizes,
             const float4* __restrict__ deltas)
{
    int b = blockIdx.x;
    if (g_done[b]) return;
    extern __shared__ unsigned long long sk[];
    unsigned cA = min(g_cntA[b], (unsigned)CAPA);
    unsigned cnt = min(g_cntB[b], (unsigned)CAPB);
    for (int p = threadIdx.x; p < CAPB; p += 1024)
        sk[p] = (p < (int)cnt) ? g_bufB[(size_t)b * CAPB + p] : ~0ull;
    __syncthreads();
    bitonic_sort<CAPB>(sk);
    float H = (float)sizes[2 * b];
    float W = (float)sizes[2 * b + 1];
    for (int p = threadIdx.x; p < (int)cnt; p += 1024) {
        int o = (int)cA + p;
        if (o < PRE_K) {
            int gi = (int)(sk[p] & 0x1FFFFFu);
            bool valid;
            float4 box = decode_box(anchors[gi], deltas[gi], W, H, valid);
            g_cidx[b * PRE_K + o] = gi;
            g_cboxes[b * PRE_K + o] = box;
        }
    }
}

// ---------------- IoU suppression bitmask (transposed, coalesced stores) -------
template<bool PHASE2>
__global__ __launch_bounds__(256)
void k_mask()
{
    int b = blockIdx.z, rs = blockIdx.y, cb = blockIdx.x;
    if (PHASE2) {
        if (g_done[b]) return;
        if (rs < MW / 256 && cb < MWW) return;       // phase-1 already covered
    }
    if (cb < rs * 4) return;                          // stripe below diagonal
    __shared__ float4 sbx[64];
    __shared__ float  sar[64];
    __shared__ float  sc7[64];
    int t = threadIdx.x;
    int cbase = cb * 64;
    int ncol = min(64, PRE_K - cbase);
    if (t < ncol) {
        float4 v = g_cboxes[b * PRE_K + cbase + t];
        sbx[t] = v;
        float ar = __fmul_rn(__fsub_rn(v.z, v.x), __fsub_rn(v.w, v.y));
        sar[t] = ar;
        sc7[t] = 0.7f * ar;
    }
    __syncthreads();
    int i = rs * 256 + t;
    if (i >= PRE_K) return;
    int rg = i >> 6;
    if (cb < rg) return;
    float4 bi_ = g_cboxes[b * PRE_K + i];
    float ai = __fmul_rn(__fsub_rn(bi_.z, bi_.x), __fsub_rn(bi_.w, bi_.y));
    float c_a = fmaf(0.7f, ai, 7e-10f);
    unsigned long long bits = 0;
    #pragma unroll 4
    for (int j = 0; j < ncol; j++) {
        float4 bj = sbx[j];
        float ix1 = fmaxf(bi_.x, bj.x), iy1 = fmaxf(bi_.y, bj.y);
        float ix2 = fminf(bi_.z, bj.z), iy2 = fminf(bi_.w, bj.w);
        float wx = fmaxf(__fsub_rn(ix2, ix1), 0.0f);
        float wy = fmaxf(__fsub_rn(iy2, iy1), 0.0f);
        float inter = __fmul_rn(wx, wy);
        float csum = sc7[j] + c_a;
        float diff = fmaf(1.7f, inter, -csum);
        bool sup;
        if (fabsf(diff) <= 1e-4f * csum) {            // borderline: exact ref math
            float denom = __fadd_rn(__fsub_rn(__fadd_rn(sar[j], ai), inter), 1e-9f);
            sup = __fdiv_rn(inter, denom) > 0.7f;
        } else {
            sup = diff > 0.0f;
        }
        if (sup) bits |= 1ull << j;
    }
    g_mask[((size_t)b * MASKW + cb) * PRE_K + i] = bits;   // coalesced over i
    unsigned long long nonself = bits;
    if (cb == rg) nonself &= ~(1ull << (i - cbase));
    if (nonself)
        atomicOr(&g_sranyb[b * MASKW + rg], 1ull << (i & 63)); // rare
}

// ---------------- NMS core: word-bulk greedy scan ------------------------------
template<int NW>
__device__ __forceinline__ int nms_core(int b, int lane, int nscan,
                                        const unsigned long long* srany,
                                        unsigned long long* rem, int outb)
{
    const unsigned long long* mbase = g_mask + (size_t)b * MASKW * PRE_K;
    int nk = 0;
    for (int w = 0; w * 64 < nscan && nk < POST_K; w++) {
        int nb = nscan - w * 64;
        unsigned long long validb = (nb >= 64) ? ~0ull : ((1ull << nb) - 1ull);
        unsigned long long any = srany[w];
        unsigned long long cand = ~rem[w] & validb;
        // prefetch likely suppressor rows (strided gather, hide latency)
        unsigned long long pf = cand & any;
        int np = 0;
        while (pf && np < 3) {
            int j = __ffsll(pf) - 1; pf &= pf - 1; np++;
            const unsigned long long* m = mbase + (w * 64 + j);
            if (lane < ((NW < 32) ? NW : 32))
                asm volatile("prefetch.global.L2 [%0];"
                             :: "l"(m + (size_t)(w + lane) * PRE_K));
        }
        while (cand && nk < POST_K) {
            unsigned long long sup = cand & any;
            unsigned long long keep;
            int s = -1;
            if (sup) {
                s = __ffsll(sup) - 1;
                keep = cand & ((s == 63) ? ~0ull : ((1ull << (s + 1)) - 1ull));
            } else {
                keep = cand;
            }
            int cnt = __popcll(keep);
            if (nk + cnt > POST_K) cnt = POST_K - nk;
            for (int r = lane; r < cnt; r += 32)
                g_kept[outb + nk + r] = w * 64 + fns64(keep, r);
            nk += cnt;
            if (nk >= POST_K) break;
            if (sup) {
                const unsigned long long* m = mbase + (w * 64 + s);
                for (int wi = w + lane; wi < NW; wi += 32)
                    rem[wi] |= m[(size_t)wi * PRE_K];
                __syncwarp();
                unsigned long long above = (s < 63) ? (~0ull << (s + 1)) : 0ull;
                cand = cand & above & ~rem[w];
            } else {
                cand = 0;
            }
        }
    }
    return nk;
}

// ---------------- phase-1 NMS over first MW candidates -------------------------
__global__ __launch_bounds__(32)
void k_nms1()
{
    int b = blockIdx.x;
    int lane = threadIdx.x;
    unsigned cA = min(g_cntA[b], (unsigned)CAPA);
    unsigned cB = min(g_cntB[b], (unsigned)CAPB);
    int nvalid = min((int)(cA + cB), PRE_K);
    int nscan = min(min((int)cA, MW), nvalid);

    __shared__ unsigned long long srany[MWW];
    __shared__ unsigned long long rem[MWW];
    for (int w = lane; w < MWW; w += 32) {
        srany[w] = g_sranyb[b * MASKW + w];
        rem[w] = 0ull;
    }
    __syncwarp();
    int nk = nms_core<MWW>(b, lane, nscan, srany, rem, b * POST_K);
    if (lane == 0) g_done[b] = (nk >= POST_K) || (nscan >= nvalid);
    for (int t = nk + lane; t < POST_K; t += 32) g_kept[b * POST_K + t] = -1;
}

// ---------------- full NMS fallback (skipped when done) ------------------------
__global__ __launch_bounds__(32)
void k_nms2()
{
    int b = blockIdx.x;
    if (g_done[b]) return;
    int lane = threadIdx.x;
    unsigned cA = min(g_cntA[b], (unsigned)CAPA);
    unsigned cB = min(g_cntB[b], (unsigned)CAPB);
    int nvalid = min((int)(cA + cB), PRE_K);

    __shared__ unsigned long long srany[MASKW];
    __shared__ unsigned long long rem[MASKW];
    for (int w = lane; w < MASKW; w += 32) {
        srany[w] = g_sranyb[b * MASKW + w];
        rem[w] = 0ull;
    }
    __syncwarp();
    int nk = nms_core<MASKW>(b, lane, nvalid, srany, rem, b * POST_K);
    for (int t = nk + lane; t < POST_K; t += 32) g_kept[b * POST_K + t] = -1;
}

// ---------------- write outputs -------------------------------------------------
__global__ __launch_bounds__(256)
void k_out(const float* __restrict__ logits, const float4* __restrict__ deltas,
           float* __restrict__ out, int B)
{
    int t = blockIdx.x * blockDim.x + threadIdx.x;
    int P = B * POST_K;
    if (t >= P) return;
    int b = t / POST_K;
    int j = g_kept[t];
    float4 pb = make_float4(0, 0, 0, 0), dl = make_float4(0, 0, 0, 0);
    float ob = 0.0f, bi = -1.0f, okf = 0.0f;
    if (j >= 0) {
        int gi = g_cidx[b * PRE_K + j];
        pb = g_cboxes[b * PRE_K + j];
        ob = logits[gi];
        dl = deltas[gi];
        bi = (float)b;
        okf = 1.0f;
    }
    ((float4*)out)[t] = pb;
    out[4 * P + t] = bi;
    out[5 * P + t] = ob;
    ((float4*)(out + 6 * P))[t] = dl;
    out[10 * P + t] = okf;
}

// ---------------- launcher ------------------------------------------------------
extern "C" void kernel_launch(void* const* d_in, const int* in_sizes, int n_in,
                              void* d_out, int out_size)
{
    const float4* anchors = (const float4*)d_in[0];
    const int*    bidx    = (const int*)d_in[1];
    const int*    sizes   = (const int*)d_in[2];
    const float*  logits  = (const float*)d_in[3];
    const float4* deltas  = (const float4*)d_in[4];
    float* out = (float*)d_out;

    int N = in_sizes[0] / 4;
    int B = in_sizes[2] / 2;
    if (N > MAXN) N = MAXN;
    if (B > MAXB) B = MAXB;

    cudaFuncSetAttribute(k_sortB, cudaFuncAttributeMaxDynamicSharedMemorySize,
                         CAPB * 8);

    k_init1<<<(B * NBINS / 2 + 255) / 256, 256>>>(B);               // 0
    k_init2<<<(B * NBINS / 2 + 255) / 256, 256>>>(B);               // 1
    k_segstart<<<1, 32>>>(bidx, N, B);                              // 2
    k_decode<<<(N + 1023) / 1024, 256>>>(anchors, sizes, logits, deltas, N, B); // 3: profiled
    k_thresh<<<B, 256>>>();
    k_compact<<<(N + 1023) / 1024, 256>>>(N, B);
    k_sortA<<<B, 1024>>>(anchors, sizes, deltas);
    k_mask<false><<<dim3(MWW, MW / 256, B), 256>>>();
    k_nms1<<<B, 32>>>();
    k_sortB<<<B, 1024, CAPB * 8>>>(anchors, sizes, deltas);
    k_mask<true><<<dim3(MASKW, (PRE_K + 255) / 256, B), 256>>>();
    k_nms2<<<B, 32>>>();
    k_out<<<(B * POST_K + 255) / 256, 256>>>(logits, deltas, out, B);
}

// round 15
// speedup vs baseline: 1.1863x; 1.1863x over previous
#include <cuda_runtime.h>

#define MAXN 1600000
#define MAXB 8
#define PRE_K 6000
#define POST_K 1000
#define MASKW 94            // ceil(6000/64) words per mask row
#define MW 1280             // phase-1 NMS scan/mask window
#define MWW 20              // MW/64
#define C1SPLIT 1280        // A/B split target == scan window
#define NBINS 4096
#define CAPA 2048           // A sorted by 2048-wide bitonic
#define CAPB 8192           // B sorted by 8192-wide bitonic (fallback only)
#define NEGV  -1000000000.0f

// ---------------- static device scratch (no allocations allowed) ----------------
__device__ float              g_score[MAXN];          // valid ? logit : NEGV
__device__ unsigned int       g_hist[MAXB * NBINS];
__device__ int                g_segstart[MAXB + 1];
__device__ int                g_t[MAXB];
__device__ int                g_t2[MAXB];
__device__ unsigned int       g_cntA[MAXB];
__device__ unsigned int       g_cntB[MAXB];
__device__ unsigned long long g_bufA[(size_t)MAXB * CAPA];
__device__ unsigned long long g_bufB[(size_t)MAXB * CAPB];
__device__ float4             g_cboxes[MAXB * PRE_K];
__device__ int                g_cidx[MAXB * PRE_K];
__device__ unsigned long long g_sranyb[MAXB * MASKW];  // "row suppresses someone" bits
__device__ unsigned long long g_mask[(size_t)MAXB * MASKW * PRE_K]; // TRANSPOSED [b][word][row]
__device__ int                g_kept[MAXB * POST_K];
__device__ int                g_done[MAXB];

// ---------------- XLA-exact sigmoid: 0.5 + 0.5*tanh(0.5x), fast-tanh poly ------
__device__ __forceinline__ float xla_tanh(float x) {
    float ax = fabsf(x);
    float xc = fminf(fmaxf(x, -7.99881172180175781f), 7.99881172180175781f);
    float x2 = __fmul_rn(xc, xc);
    float p = fmaf(x2, -2.76076847742355e-16f, 2.00018790482477e-13f);
    p = fmaf(p, x2, -8.60467152213735e-11f);
    p = fmaf(p, x2,  5.12229709037114e-08f);
    p = fmaf(p, x2,  1.48572235717979e-05f);
    p = fmaf(p, x2,  6.37261928875436e-04f);
    p = fmaf(p, x2,  4.89352455891786e-03f);
    float num = __fmul_rn(xc, p);
    float q = fmaf(x2, 1.19825839466702e-06f, 1.18534705686654e-04f);
    q = fmaf(q, x2, 2.26843463243900e-03f);
    q = fmaf(q, x2, 4.89352518554385e-03f);
    float r = __fdiv_rn(num, q);
    return (ax < 0.0004f) ? x : r;
}
__device__ __forceinline__ float xla_sigmoid(float x) {
    float t = xla_tanh(__fmul_rn(0.5f, x));
    return __fadd_rn(__fmul_rn(0.5f, t), 0.5f);
}

// monotone logit-space bin; bin 0 reserved for invalid (never consulted, g_t >= 1)
__device__ __forceinline__ int logit_bin(float lg) {
    int v = (int)__fmul_rn(__fadd_rn(lg, 6.0f), 341.0f);
    if (v < 1) v = 1;
    if (v > NBINS - 1) v = NBINS - 1;
    return v;
}
__device__ __forceinline__ unsigned score_key(float s) {
    unsigned ub = __float_as_uint(s);
    return (ub & 0x80000000u) ? ~ub : (ub | 0x80000000u);
}
// image id from sorted batch_indices boundaries (7 L1-hot compares)
__device__ __forceinline__ int find_b(int i, int B) {
    int b = 0;
    #pragma unroll
    for (int k = 1; k < MAXB; k++)
        if (k < B && i >= g_segstart[k]) b = k;
    return b;
}
// r-th (0-based) set bit of a 64-bit mask
__device__ __forceinline__ int fns64(unsigned long long m, int r) {
    unsigned lo = (unsigned)m;
    int pl = __popc(lo);
    if (r < pl) return (int)__fns(lo, 0, r + 1);
    return 32 + (int)__fns((unsigned)(m >> 32), 0, r - pl + 1);
}

// exact reference box decode (bit-exact path)
__device__ __forceinline__ float4 decode_box(float4 a, float4 d, float W, float H,
                                             bool& valid)
{
    float aw = __fsub_rn(a.z, a.x);
    float ah = __fsub_rn(a.w, a.y);
    float ax = __fadd_rn(a.x, __fmul_rn(0.5f, aw));
    float ay = __fadd_rn(a.y, __fmul_rn(0.5f, ah));
    float px = __fadd_rn(ax, __fmul_rn(d.x, aw));
    float py = __fadd_rn(ay, __fmul_rn(d.y, ah));
    float twc = fminf(fmaxf(d.z, -10.0f), 10.0f);
    float thc = fminf(fmaxf(d.w, -10.0f), 10.0f);
    float pw = __fmul_rn(aw, expf(twc));
    float ph = __fmul_rn(ah, expf(thc));
    float x1 = __fsub_rn(px, __fmul_rn(0.5f, pw));
    float y1 = __fsub_rn(py, __fmul_rn(0.5f, ph));
    float x2 = __fadd_rn(px, __fmul_rn(0.5f, pw));
    float y2 = __fadd_rn(py, __fmul_rn(0.5f, ph));
    float Wm1 = __fsub_rn(W, 1.0f);
    float Hm1 = __fsub_rn(H, 1.0f);
    x1 = fminf(fmaxf(x1, 0.0f), Wm1);
    y1 = fminf(fmaxf(y1, 0.0f), Hm1);
    x2 = fminf(fmaxf(x2, 0.0f), Wm1);
    y2 = fminf(fmaxf(y2, 0.0f), Hm1);
    valid = (__fsub_rn(x2, x1) >= 16.0f) && (__fsub_rn(y2, y1) >= 16.0f);
    return make_float4(x1, y1, x2, y2);
}

// fast validity: __expf + contracted ops; exact recompute inside a guard band
// around the 16.0 decision boundary (band covers 3x the propagated approx error)
__device__ __forceinline__ bool fast_valid(float4 a, float4 d, float W, float H)
{
    float aw = a.z - a.x, ah = a.w - a.y;
    float ax = a.x + 0.5f * aw, ay = a.y + 0.5f * ah;
    float px = ax + d.x * aw, py = ay + d.y * ah;
    float twc = fminf(fmaxf(d.z, -10.0f), 10.0f);
    float thc = fminf(fmaxf(d.w, -10.0f), 10.0f);
    float pw = aw * __expf(twc);
    float ph = ah * __expf(thc);
    float x1 = px - 0.5f * pw, y1 = py - 0.5f * ph;
    float x2 = px + 0.5f * pw, y2 = py + 0.5f * ph;
    float Wm1 = W - 1.0f, Hm1 = H - 1.0f;
    x1 = fminf(fmaxf(x1, 0.0f), Wm1);
    y1 = fminf(fmaxf(y1, 0.0f), Hm1);
    x2 = fminf(fmaxf(x2, 0.0f), Wm1);
    y2 = fminf(fmaxf(y2, 0.0f), Hm1);
    float vx = x2 - x1, vy = y2 - y1;
    float band = fmaf(3e-6f, pw + ph, 0.05f);
    if (fabsf(vx - 16.0f) < band || fabsf(vy - 16.0f) < band) {
        bool valid;
        decode_box(a, d, W, H, valid);   // rare: bit-exact decision
        return valid;
    }
    return (vx >= 16.0f) && (vy >= 16.0f);
}

// ---------------- bitonic sort of NS u64 keys in shared memory (1024 thr) ------
template<int NS>
__device__ __forceinline__ void bitonic_sort(unsigned long long* sk)
{
    #pragma unroll 1
    for (int k = 2; k <= NS; k <<= 1) {
        #pragma unroll 1
        for (int j = k >> 1; j > 0; j >>= 1) {
            #pragma unroll
            for (int it = 0; it < (NS / 2 + 1023) / 1024; it++) {
                int t = threadIdx.x + it * 1024;
                if (t < NS / 2) {
                    int i = ((t & ~(j - 1)) << 1) | (t & (j - 1));
                    int p = i + j;
                    bool up = ((i & k) == 0);
                    unsigned long long a = sk[i], c = sk[p];
                    if ((a > c) == up) { sk[i] = c; sk[p] = a; }
                }
            }
            __syncthreads();
        }
    }
}

// ---------------- launches 0/1: init -------------------------------------------
__global__ void k_init1(int B)
{
    int t = blockIdx.x * blockDim.x + threadIdx.x;
    if (t < B * NBINS / 2) g_hist[t] = 0;
}
__global__ void k_init2(int B)
{
    int t = blockIdx.x * blockDim.x + threadIdx.x;
    if (t < B * NBINS / 2) g_hist[B * NBINS / 2 + t] = 0;
    if (t < B * MASKW) g_sranyb[t] = 0ull;
}
// ---------------- launch 2: segment boundaries (batch_indices sorted) ----------
__global__ void k_segstart(const int* __restrict__ bi, int N, int B)
{
    int t = threadIdx.x;
    if (t > B) return;
    if (t == B) { g_segstart[B] = N; return; }
    int lo = 0, hi = N;
    while (lo < hi) { int mid = (lo + hi) >> 1; if (bi[mid] < t) lo = mid + 1; else hi = mid; }
    g_segstart[t] = lo;
}

// ---------------- launch 3 (profiled): decode, 4 elems/thread ------------------
__global__ __launch_bounds__(256)
void k_decode(const float4* __restrict__ anchors, const int* __restrict__ sizes,
              const float* __restrict__ logits, const float4* __restrict__ deltas,
              int N, int B)
{
    int base = (blockIdx.x * blockDim.x + threadIdx.x) * 4;
    if (base >= N) return;
    if (base + 4 <= N) {
        float4 a[4], d[4];
        a[0] = anchors[base];   a[1] = anchors[base+1];
        a[2] = anchors[base+2]; a[3] = anchors[base+3];
        d[0] = deltas[base];    d[1] = deltas[base+1];
        d[2] = deltas[base+2];  d[3] = deltas[base+3];
        float4 lg = *(const float4*)(logits + base);
        float lgs[4] = {lg.x, lg.y, lg.z, lg.w};
        int b0 = find_b(base, B), b3 = find_b(base + 3, B);
        float sc[4];
        if (b0 == b3) {                       // uniform quad (overwhelmingly common)
            float H = (float)sizes[2 * b0];
            float W = (float)sizes[2 * b0 + 1];
            #pragma unroll
            for (int e = 0; e < 4; e++) {
                bool valid = fast_valid(a[e], d[e], W, H);
                sc[e] = valid ? lgs[e] : NEGV;
                if (valid)
                    atomicAdd(&g_hist[b0 * NBINS + logit_bin(lgs[e])], 1u);
            }
        } else {                              // segment boundary quad (rare)
            #pragma unroll
            for (int e = 0; e < 4; e++) {
                int b = find_b(base + e, B);
                float H = (float)sizes[2 * b];
                float W = (float)sizes[2 * b + 1];
                bool valid = fast_valid(a[e], d[e], W, H);
                sc[e] = valid ? lgs[e] : NEGV;
                if (valid)
                    atomicAdd(&g_hist[b * NBINS + logit_bin(lgs[e])], 1u);
            }
        }
        *(float4*)(g_score + base) = make_float4(sc[0], sc[1], sc[2], sc[3]);
    } else {
        for (int i = base; i < N; i++) {
            int b = find_b(i, B);
            float H = (float)sizes[2 * b];
            float W = (float)sizes[2 * b + 1];
            bool valid = fast_valid(anchors[i], deltas[i], W, H);
            float lg = logits[i];
            g_score[i] = valid ? lg : NEGV;
            if (valid)
                atomicAdd(&g_hist[b * NBINS + logit_bin(lg)], 1u);
        }
    }
}

// ---------------- thresholds ---------------------------------------------------
__global__ __launch_bounds__(256)
void k_thresh()
{
    int b = blockIdx.x;
    int t = threadIdx.x;
    unsigned v[16]; unsigned s = 0;
    for (int k = 0; k < 16; k++) {
        v[k] = g_hist[b * NBINS + (NBINS - 1 - (t * 16 + k))];
        s += v[k];
    }
    __shared__ unsigned ps[256];
    __shared__ int s_t, s_t2;
    if (t == 0) { s_t = 1; s_t2 = 1; }
    ps[t] = s; __syncthreads();
    for (int off = 1; off < 256; off <<= 1) {
        unsigned x = (t >= off) ? ps[t - off] : 0u;
        __syncthreads();
        ps[t] += x;
        __syncthreads();
    }
    unsigned cum = ps[t] - s;        // exclusive prefix (descending bins)
    for (int k = 0; k < 16; k++) {
        unsigned nc = cum + v[k];
        int bin = NBINS - 1 - (t * 16 + k);
        if (cum < C1SPLIT && nc >= C1SPLIT) s_t2 = bin;
        if (cum < PRE_K   && nc >= PRE_K)   s_t  = bin;
        cum = nc;
    }
    __syncthreads();
    if (t == 0) {
        int tt = s_t, tt2 = s_t2;
        if (tt < 1) tt = 1;
        if (tt2 <= tt) tt2 = tt + 1;
        g_t[b] = tt; g_t2[b] = tt2;
        g_cntA[b] = 0; g_cntB[b] = 0;
        g_done[b] = 0;
    }
}

// ---------------- compact candidates (sigmoid only here) -----------------------
__global__ __launch_bounds__(256)
void k_compact(int N, int B)
{
    int base = (blockIdx.x * blockDim.x + threadIdx.x) * 4;
    if (base >= N) return;
    float4 s4 = *(const float4*)(g_score + base);
    float sv[4] = {s4.x, s4.y, s4.z, s4.w};
    #pragma unroll
    for (int k = 0; k < 4; k++) {
        int i = base + k;
        bool pass = false;
        int b = 0; bool toA = false;
        if (i < N && sv[k] > -1e8f) {
            b = find_b(i, B);
            int bin = logit_bin(sv[k]);
            if (bin >= g_t[b]) { pass = true; toA = (bin >= g_t2[b]); }
        }
        unsigned am = __activemask();
        unsigned grp = __ballot_sync(am, pass);
        if (!pass) continue;
        unsigned same = __match_any_sync(grp, b * 2 + (toA ? 1 : 0)) & grp;
        int leader = __ffs(same) - 1;
        int lane = threadIdx.x & 31;
        unsigned pos = 0;
        unsigned* ctr = toA ? &g_cntA[b] : &g_cntB[b];
        if (lane == leader) pos = atomicAdd(ctr, (unsigned)__popc(same));
        pos = __shfl_sync(grp, pos, leader);
        pos += __popc(same & ((1u << lane) - 1u));
        unsigned long long key =
            ((unsigned long long)(~score_key(xla_sigmoid(sv[k]))) << 21) | (unsigned)i;
        if (toA) { if (pos < CAPA) g_bufA[(size_t)b * CAPA + pos] = key; }
        else     { if (pos < CAPB) g_bufB[(size_t)b * CAPB + pos] = key; }
    }
}

// ---------------- sort A (2048 bitonic) + recompute candidate boxes ------------
__global__ __launch_bounds__(1024)
void k_sortA(const float4* __restrict__ anchors, const int* __restrict__ sizes,
             const float4* __restrict__ deltas)
{
    __shared__ unsigned long long sk[CAPA];
    int b = blockIdx.x;
    unsigned cnt = min(g_cntA[b], (unsigned)CAPA);
    for (int p = threadIdx.x; p < CAPA; p += 1024)
        sk[p] = (p < (int)cnt) ? g_bufA[(size_t)b * CAPA + p] : ~0ull;
    __syncthreads();
    bitonic_sort<CAPA>(sk);
    float H = (float)sizes[2 * b];
    float W = (float)sizes[2 * b + 1];
    for (int p = threadIdx.x; p < (int)cnt; p += 1024) {
        int gi = (int)(sk[p] & 0x1FFFFFu);
        bool valid;
        float4 box = decode_box(anchors[gi], deltas[gi], W, H, valid);
        g_cidx[b * PRE_K + p] = gi;
        g_cboxes[b * PRE_K + p] = box;
    }
}

// ---------------- sort B (8192 bitonic, fallback only) -------------------------
__global__ __launch_bounds__(1024)
void k_sortB(const float4* __restrict__ anchors, const int* __restrict__ sizes,
             const float4* __restrict__ deltas)
{
    int b = blockIdx.x;
    if (g_done[b]) return;
    extern __shared__ unsigned long long sk[];
    unsigned cA = min(g_cntA[b], (unsigned)CAPA);
    unsigned cnt = min(g_cntB[b], (unsigned)CAPB);
    for (int p = threadIdx.x; p < CAPB; p += 1024)
        sk[p] = (p < (int)cnt) ? g_bufB[(size_t)b * CAPB + p] : ~0ull;
    __syncthreads();
    bitonic_sort<CAPB>(sk);
    float H = (float)sizes[2 * b];
    float W = (float)sizes[2 * b + 1];
    for (int p = threadIdx.x; p < (int)cnt; p += 1024) {
        int o = (int)cA + p;
        if (o < PRE_K) {
            int gi = (int)(sk[p] & 0x1FFFFFu);
            bool valid;
            float4 box = decode_box(anchors[gi], deltas[gi], W, H, valid);
            g_cidx[b * PRE_K + o] = gi;
            g_cboxes[b * PRE_K + o] = box;
        }
    }
}

// ---------------- IoU suppression bitmask (transposed, coalesced stores) -------
template<bool PHASE2>
__global__ __launch_bounds__(256)
void k_mask()
{
    int b = blockIdx.z, rs = blockIdx.y, cb = blockIdx.x;
    if (PHASE2) {
        if (g_done[b]) return;
        if (rs < MW / 256 && cb < MWW) return;       // phase-1 already covered
    }
    if (cb < rs * 4) return;                          // stripe below diagonal
    __shared__ float4 sbx[64];
    __shared__ float  sar[64];
    __shared__ float  sc7[64];
    int t = threadIdx.x;
    int cbase = cb * 64;
    int ncol = min(64, PRE_K - cbase);
    if (t < ncol) {
        float4 v = g_cboxes[b * PRE_K + cbase + t];
        sbx[t] = v;
        float ar = __fmul_rn(__fsub_rn(v.z, v.x), __fsub_rn(v.w, v.y));
        sar[t] = ar;
        sc7[t] = 0.7f * ar;
    }
    __syncthreads();
    int i = rs * 256 + t;
    if (i >= PRE_K) return;
    int rg = i >> 6;
    if (cb < rg) return;
    float4 bi_ = g_cboxes[b * PRE_K + i];
    float ai = __fmul_rn(__fsub_rn(bi_.z, bi_.x), __fsub_rn(bi_.w, bi_.y));
    float c_a = fmaf(0.7f, ai, 7e-10f);
    unsigned long long bits = 0;
    #pragma unroll 4
    for (int j = 0; j < ncol; j++) {
        float4 bj = sbx[j];
        float ix1 = fmaxf(bi_.x, bj.x), iy1 = fmaxf(bi_.y, bj.y);
        float ix2 = fminf(bi_.z, bj.z), iy2 = fminf(bi_.w, bj.w);
        float wx = fmaxf(__fsub_rn(ix2, ix1), 0.0f);
        float wy = fmaxf(__fsub_rn(iy2, iy1), 0.0f);
        float inter = __fmul_rn(wx, wy);
        float csum = sc7[j] + c_a;
        float diff = fmaf(1.7f, inter, -csum);
        bool sup;
        if (fabsf(diff) <= 1e-4f * csum) {            // borderline: exact ref math
            float denom = __fadd_rn(__fsub_rn(__fadd_rn(sar[j], ai), inter), 1e-9f);
            sup = __fdiv_rn(inter, denom) > 0.7f;
        } else {
            sup = diff > 0.0f;
        }
        if (sup) bits |= 1ull << j;
    }
    g_mask[((size_t)b * MASKW + cb) * PRE_K + i] = bits;   // coalesced over i
    unsigned long long nonself = bits;
    if (cb == rg) nonself &= ~(1ull << (i - cbase));
    if (nonself)
        atomicOr(&g_sranyb[b * MASKW + rg], 1ull << (i & 63)); // rare
}

// ---------------- NMS core: word-bulk greedy scan ------------------------------
template<int NW>
__device__ __forceinline__ int nms_core(int b, int lane, int nscan,
                                        const unsigned long long* srany,
                                        unsigned long long* rem, int outb)
{
    const unsigned long long* mbase = g_mask + (size_t)b * MASKW * PRE_K;
    int nk = 0;
    for (int w = 0; w * 64 < nscan && nk < POST_K; w++) {
        int nb = nscan - w * 64;
        unsigned long long validb = (nb >= 64) ? ~0ull : ((1ull << nb) - 1ull);
        unsigned long long any = srany[w];
        unsigned long long cand = ~rem[w] & validb;
        // prefetch likely suppressor rows (strided gather, hide latency)
        unsigned long long pf = cand & any;
        int np = 0;
        while (pf && np < 3) {
            int j = __ffsll(pf) - 1; pf &= pf - 1; np++;
            const unsigned long long* m = mbase + (w * 64 + j);
            if (lane < ((NW < 32) ? NW : 32))
                asm volatile("prefetch.global.L2 [%0];"
                             :: "l"(m + (size_t)(w + lane) * PRE_K));
        }
        while (cand && nk < POST_K) {
            unsigned long long sup = cand & any;
            unsigned long long keep;
            int s = -1;
            if (sup) {
                s = __ffsll(sup) - 1;
                keep = cand & ((s == 63) ? ~0ull : ((1ull << (s + 1)) - 1ull));
            } else {
                keep = cand;
            }
            int cnt = __popcll(keep);
            if (nk + cnt > POST_K) cnt = POST_K - nk;
            for (int r = lane; r < cnt; r += 32)
                g_kept[outb + nk + r] = w * 64 + fns64(keep, r);
            nk += cnt;
            if (nk >= POST_K) break;
            if (sup) {
                const unsigned long long* m = mbase + (w * 64 + s);
                for (int wi = w + lane; wi < NW; wi += 32)
                    rem[wi] |= m[(size_t)wi * PRE_K];
                __syncwarp();
                unsigned long long above = (s < 63) ? (~0ull << (s + 1)) : 0ull;
                cand = cand & above & ~rem[w];
            } else {
                cand = 0;
            }
        }
    }
    return nk;
}

// ---------------- phase-1 NMS over first MW candidates -------------------------
__global__ __launch_bounds__(32)
void k_nms1()
{
    int b = blockIdx.x;
    int lane = threadIdx.x;
    unsigned cA = min(g_cntA[b], (unsigned)CAPA);
    unsigned cB = min(g_cntB[b], (unsigned)CAPB);
    int nvalid = min((int)(cA + cB), PRE_K);
    int nscan = min(min((int)cA, MW), nvalid);

    __shared__ unsigned long long srany[MWW];
    __shared__ unsigned long long rem[MWW];
    for (int w = lane; w < MWW; w += 32) {
        srany[w] = g_sranyb[b * MASKW + w];
        rem[w] = 0ull;
    }
    __syncwarp();
    int nk = nms_core<MWW>(b, lane, nscan, srany, rem, b * POST_K);
    if (lane == 0) g_done[b] = (nk >= POST_K) || (nscan >= nvalid);
    for (int t = nk + lane; t < POST_K; t += 32) g_kept[b * POST_K + t] = -1;
}

// ---------------- full NMS fallback (skipped when done) ------------------------
__global__ __launch_bounds__(32)
void k_nms2()
{
    int b = blockIdx.x;
    if (g_done[b]) return;
    int lane = threadIdx.x;
    unsigned cA = min(g_cntA[b], (unsigned)CAPA);
    unsigned cB = min(g_cntB[b], (unsigned)CAPB);
    int nvalid = min((int)(cA + cB), PRE_K);

    __shared__ unsigned long long srany[MASKW];
    __shared__ unsigned long long rem[MASKW];
    for (int w = lane; w < MASKW; w += 32) {
        srany[w] = g_sranyb[b * MASKW + w];
        rem[w] = 0ull;
    }
    __syncwarp();
    int nk = nms_core<MASKW>(b, lane, nvalid, srany, rem, b * POST_K);
    for (int t = nk + lane; t < POST_K; t += 32) g_kept[b * POST_K + t] = -1;
}

// ---------------- write outputs -------------------------------------------------
__global__ __launch_bounds__(256)
void k_out(const float* __restrict__ logits, const float4* __restrict__ deltas,
           float* __restrict__ out, int B)
{
    int t = blockIdx.x * blockDim.x + threadIdx.x;
    int P = B * POST_K;
    if (t >= P) return;
    int b = t / POST_K;
    int j = g_kept[t];
    float4 pb = make_float4(0, 0, 0, 0), dl = make_float4(0, 0, 0, 0);
    float ob = 0.0f, bi = -1.0f, okf = 0.0f;
    if (j >= 0) {
        int gi = g_cidx[b * PRE_K + j];
        pb = g_cboxes[b * PRE_K + j];
        ob = logits[gi];
        dl = deltas[gi];
        bi = (float)b;
        okf = 1.0f;
    }
    ((float4*)out)[t] = pb;
    out[4 * P + t] = bi;
    out[5 * P + t] = ob;
    ((float4*)(out + 6 * P))[t] = dl;
    out[10 * P + t] = okf;
}

// ---------------- launcher ------------------------------------------------------
extern "C" void kernel_launch(void* const* d_in, const int* in_sizes, int n_in,
                              void* d_out, int out_size)
{
    const float4* anchors = (const float4*)d_in[0];
    const int*    bidx    = (const int*)d_in[1];
    const int*    sizes   = (const int*)d_in[2];
    const float*  logits  = (const float*)d_in[3];
    const float4* deltas  = (const float4*)d_in[4];
    float* out = (float*)d_out;

    int N = in_sizes[0] / 4;
    int B = in_sizes[2] / 2;
    if (N > MAXN) N = MAXN;
    if (B > MAXB) B = MAXB;

    cudaFuncSetAttribute(k_sortB, cudaFuncAttributeMaxDynamicSharedMemorySize,
                         CAPB * 8);

    k_init1<<<(B * NBINS / 2 + 255) / 256, 256>>>(B);               // 0
    k_init2<<<(B * NBINS / 2 + 255) / 256, 256>>>(B);               // 1
    k_segstart<<<1, 32>>>(bidx, N, B);                              // 2
    k_decode<<<(N + 1023) / 1024, 256>>>(anchors, sizes, logits, deltas, N, B); // 3: profiled
    k_thresh<<<B, 256>>>();
    k_compact<<<(N + 1023) / 1024, 256>>>(N, B);
    k_sortA<<<B, 1024>>>(anchors, sizes, deltas);
    k_mask<false><<<dim3(MWW, MW / 256, B), 256>>>();
    k_nms1<<<B, 32>>>();
    k_sortB<<<B, 1024, CAPB * 8>>>(anchors, sizes, deltas);
    k_mask<true><<<dim3(MASKW, (PRE_K + 255) / 256, B), 256>>>();
    k_nms2<<<B, 32>>>();
    k_out<<<(B * POST_K + 255) / 256, 256>>>(logits, deltas, out, B);
}